// round 15
// baseline (speedup 1.0000x reference)
#include <cuda_runtime.h>
#include <cuda_fp16.h>
#include <cstdint>

#define LSEQ 2048
#define BATCH 2
#define NH 12
#define FEATD 16
#define HD 64
#define DM 768
#define QKS 384             // combined Q|K width
#define NPROJ 1152          // merged Q|K|V projection width
#define ROWS (BATCH * LSEQ) // 4096
#define AKT 64              // attention key tile

// Scratch (no cudaMalloc allowed)
__device__ __half g_Xf[ROWS * DM];           // X single fp16
__device__ __half g_Wf[NPROJ * DM];          // merged proj weights single fp16
__device__ __half g_QKf[ROWS * QKS];         // Q|K single fp16
__device__ __half g_Vf[ROWS * DM];           // V single fp16
__device__ __half g_Yf[ROWS * DM];           // Y single fp16
__device__ __half g_Wof[DM * DM];            // Wo single fp16

// ---- helpers ----
__device__ __forceinline__ uint32_t smem_u32(const void* p) {
    uint32_t a;
    asm("{ .reg .u64 t; cvta.to.shared.u64 t, %1; cvt.u32.u64 %0, t; }" : "=r"(a) : "l"(p));
    return a;
}
__device__ __forceinline__ uint32_t sw128(uint32_t o) { return o ^ ((o >> 3) & 0x70); }
__device__ __forceinline__ void ldsm_x4(uint32_t* r, uint32_t addr) {
    asm volatile("ldmatrix.sync.aligned.m8n8.x4.shared.b16 {%0,%1,%2,%3}, [%4];"
                 : "=r"(r[0]), "=r"(r[1]), "=r"(r[2]), "=r"(r[3]) : "r"(addr));
}
__device__ __forceinline__ void ldsm_x4t(uint32_t* r, uint32_t addr) {
    asm volatile("ldmatrix.sync.aligned.m8n8.x4.trans.shared.b16 {%0,%1,%2,%3}, [%4];"
                 : "=r"(r[0]), "=r"(r[1]), "=r"(r[2]), "=r"(r[3]) : "r"(addr));
}
__device__ __forceinline__ void mma_f16(float* d, const uint32_t* a, uint32_t b0, uint32_t b1) {
    asm volatile(
        "mma.sync.aligned.m16n8k16.row.col.f32.f16.f16.f32 "
        "{%0,%1,%2,%3}, {%4,%5,%6,%7}, {%8,%9}, {%0,%1,%2,%3};"
        : "+f"(d[0]), "+f"(d[1]), "+f"(d[2]), "+f"(d[3])
        : "r"(a[0]), "r"(a[1]), "r"(a[2]), "r"(a[3]), "r"(b0), "r"(b1));
}
__device__ __forceinline__ void cp16(uint32_t dst, const void* src) {
    asm volatile("cp.async.cg.shared.global [%0], [%1], 16;" :: "r"(dst), "l"(src));
}
__device__ __forceinline__ void cp_commit() { asm volatile("cp.async.commit_group;" ::: "memory"); }
template <int N> __device__ __forceinline__ void cp_wait() {
    asm volatile("cp.async.wait_group %0;" :: "n"(N) : "memory");
}
__device__ __forceinline__ uint32_t cvt2h(float lo, float hi) {
    uint32_t r; asm("cvt.rn.f16x2.f32 %0, %1, %2;" : "=r"(r) : "f"(hi), "f"(lo)); return r;
}
__device__ __forceinline__ float poly(float s) {      // weight-1 score
    return fmaf(s, fmaf(s, 0.03125f, 0.25f), 1.0f);
}
__device__ __forceinline__ float poly2(float s) {     // weight-2 folded in
    return fmaf(s, fmaf(s, 0.0625f, 0.5f), 2.0f);
}

// ---------------------------------------------------------------------------
// Converters
// ---------------------------------------------------------------------------
__global__ void __launch_bounds__(256) convert_h(
    const float* __restrict__ x, __half* __restrict__ xf)
{
    int i = (blockIdx.x * 256 + threadIdx.x) * 4;
    float4 v = *(const float4*)&x[i];
    ((uint32_t*)(xf + i))[0] = cvt2h(v.x, v.y);
    ((uint32_t*)(xf + i))[1] = cvt2h(v.z, v.w);
}

#define WQN (192 * DM)
#define WVN (DM * DM)
__global__ void __launch_bounds__(256) convert_weights(
    const float* __restrict__ Wq, const float* __restrict__ Wk,
    const float* __restrict__ Wv, const float* __restrict__ Wo,
    __half* __restrict__ Wf, __half* __restrict__ Wof)
{
    int i = (blockIdx.x * 256 + threadIdx.x) * 4;
    const float* src;
    __half* dst;
    if (i < WQN)                   { src = Wq + i;                 dst = Wf + i; }
    else if (i < 2 * WQN)          { src = Wk + (i - WQN);         dst = Wf + i; }
    else if (i < 2 * WQN + WVN)    { src = Wv + (i - 2 * WQN);     dst = Wf + i; }
    else                           { src = Wo + (i - 2 * WQN - WVN); dst = Wof + (i - 2 * WQN - WVN); }
    float4 v = *(const float4*)src;
    ((uint32_t*)dst)[0] = cvt2h(v.x, v.y);
    ((uint32_t*)dst)[1] = cvt2h(v.z, v.w);
}

// ---------------------------------------------------------------------------
// Single-pass fp16 GEMM: C[M,N] = A[M,768] @ B[N,768]^T
// CTA 128x128, 8 warps (4x2), warp 32x64, BK=64, 3-stage single-sync, occ 2.
// MODE 0: fp32 out (outproj). MODE 1: proj epilogue (QKf / Vf split by col).
// ---------------------------------------------------------------------------
#define GSTG 32768
#define G_A 0
#define G_B 16384

template <int MODE>
__global__ void __launch_bounds__(256, 2) mma_gemm(
    const __half* __restrict__ A, const __half* __restrict__ B,
    float* __restrict__ C, __half* __restrict__ QKf, __half* __restrict__ Vf)
{
    extern __shared__ char smem[];
    const uint32_t sb = smem_u32(smem);
    const int tid = threadIdx.x;
    const int wid = tid >> 5;
    const int lane = tid & 31;
    const int warpRow = wid >> 1;
    const int warpCol = wid & 1;
    const int m0 = blockIdx.y * 128;
    const int n0 = blockIdx.x * 128;

    const int lrow8 = ((lane >> 3) & 1) * 8 + (lane & 7);
    const int klane = ((lane >> 4) & 1) * 16;
    const int a_row = warpRow * 32 + lrow8;
    const int b_row = warpCol * 64 + lrow8;

    float acc[2][8][4];
#pragma unroll
    for (int mt = 0; mt < 2; mt++)
#pragma unroll
        for (int nt = 0; nt < 8; nt++)
#pragma unroll
            for (int j = 0; j < 4; j++) acc[mt][nt][j] = 0.f;

    const int NCH = DM / 64;   // 12

    // prologue: stages 0 and 1
#pragma unroll
    for (int pc = 0; pc < 2; pc++) {
        uint32_t sp = sb + pc * GSTG;
        int k0 = pc * 64;
#pragma unroll
        for (int t = 0; t < 4; t++) {
            int u = tid + t * 256;
            int r = u >> 3, cb = (u & 7) * 16;
            uint32_t sw = sw128((uint32_t)(r * 128 + cb));
            cp16(sp + G_A + sw, A + (size_t)(m0 + r) * DM + k0 + (cb >> 1));
            cp16(sp + G_B + sw, B + (size_t)(n0 + r) * DM + k0 + (cb >> 1));
        }
        cp_commit();
    }

    for (int c = 0; c < NCH; c++) {
        cp_wait<1>();
        __syncthreads();
        // issue loads for stage c+2 (writes (c+2)%3 == (c-1)%3, consumed at c-1)
        if (c + 2 < NCH) {
            uint32_t s2 = sb + ((c + 2) % 3) * GSTG;
            int k0 = (c + 2) * 64;
#pragma unroll
            for (int t = 0; t < 4; t++) {
                int u = tid + t * 256;
                int r = u >> 3, cb = (u & 7) * 16;
                uint32_t sw = sw128((uint32_t)(r * 128 + cb));
                cp16(s2 + G_A + sw, A + (size_t)(m0 + r) * DM + k0 + (cb >> 1));
                cp16(s2 + G_B + sw, B + (size_t)(n0 + r) * DM + k0 + (cb >> 1));
            }
        }
        cp_commit();

        const uint32_t sc = sb + (c % 3) * GSTG;
#pragma unroll
        for (int kt = 0; kt < 4; kt++) {
            const uint32_t kb = kt * 32 + klane;
            uint32_t a[2][4], b[4][4];
#pragma unroll
            for (int mt = 0; mt < 2; mt++)
                ldsm_x4(a[mt], sc + G_A + sw128((uint32_t)((a_row + mt * 16) * 128 + kb)));
#pragma unroll
            for (int nt2 = 0; nt2 < 4; nt2++)
                ldsm_x4(b[nt2], sc + G_B + sw128((uint32_t)((b_row + nt2 * 16) * 128 + kb)));
#pragma unroll
            for (int mt = 0; mt < 2; mt++)
#pragma unroll
                for (int nt = 0; nt < 8; nt++) {
                    int p = nt >> 1, j = nt & 1;
                    mma_f16(acc[mt][nt], a[mt], b[p][j], b[p][2 + j]);
                }
        }
    }

    const int g = lane >> 2;
    const int tc = (lane & 3) * 2;
#pragma unroll
    for (int mt = 0; mt < 2; mt++) {
        int row = m0 + warpRow * 32 + mt * 16 + g;
#pragma unroll
        for (int nt = 0; nt < 8; nt++) {
            int col = n0 + warpCol * 64 + nt * 8 + tc;
            float v0 = acc[mt][nt][0], v1 = acc[mt][nt][1];
            float v2 = acc[mt][nt][2], v3 = acc[mt][nt][3];
            if (MODE == 0) {
                *(float2*)&C[(size_t)row * DM + col] = make_float2(v0, v1);
                *(float2*)&C[(size_t)(row + 8) * DM + col] = make_float2(v2, v3);
            } else {
                if (col < QKS) {
                    *(uint32_t*)&QKf[(size_t)row * QKS + col] = cvt2h(v0, v1);
                    *(uint32_t*)&QKf[(size_t)(row + 8) * QKS + col] = cvt2h(v2, v3);
                } else {
                    int c2 = col - QKS;
                    *(uint32_t*)&Vf[(size_t)row * DM + c2] = cvt2h(v0, v1);
                    *(uint32_t*)&Vf[(size_t)(row + 8) * DM + c2] = cvt2h(v2, v3);
                }
            }
        }
    }
}

// ---------------------------------------------------------------------------
// HMMA attention (R12 shape, 3-stage single-sync pipeline):
// 8 warps x 16 query rows; S fp16 1-pass; A fp16; AV fp16 1-pass; z fp32.
// Causal modes: 2 = all weight-2 (poly2), 1 = all weight-1, 0 = mixed.
// ---------------------------------------------------------------------------
#define AQ_OFF 0                       // 128 rows * 48B = 6144
#define AK_OFF 6144                    // + st*3072   (3 stages)
#define AV_OFF 15360                   // + st*8192   (3 stages)
#define ASM_TOTAL 39936

__device__ __forceinline__ void attn_load_tile(
    uint32_t sb, int st, int m0, int tid,
    const __half* QKf, const __half* Vf, size_t rowbase, int h)
{
    if (tid < 128) {
        int r = tid >> 1, half = tid & 1;
        cp16(sb + AK_OFF + st * 3072 + r * 48 + half * 16,
             QKf + (rowbase + m0 + r) * QKS + 192 + h * FEATD + half * 8);
    }
#pragma unroll
    for (int i = 0; i < 2; i++) {
        int u = tid + i * 256;
        int r = u >> 3, ch = (u & 7) * 16;
        cp16(sb + AV_OFF + st * 8192 + sw128((uint32_t)(r * 128 + ch)),
             Vf + (rowbase + m0 + r) * DM + h * HD + (ch >> 1));
    }
}

template <int CMODE>
__device__ __forceinline__ void attn_tile_body(
    uint32_t kb, uint32_t vb, const uint32_t* qf,
    float accY[8][4], float& z0, float& z1, int relq0, int lane)
{
#pragma unroll
    for (int s = 0; s < 4; s++) {
        uint32_t koff = (uint32_t)((16 * s + ((lane >> 4) & 1) * 8 + (lane & 7)) * 48
                                   + ((lane >> 3) & 1) * 16);
        uint32_t bf[4];
        ldsm_x4(bf, kb + koff);
        float s0[4] = {0.f, 0.f, 0.f, 0.f};
        float s1[4] = {0.f, 0.f, 0.f, 0.f};
        mma_f16(s0, qf, bf[0], bf[1]);
        mma_f16(s1, qf, bf[2], bf[3]);

        float a0, a1, a2, a3, b0, b1, b2, b3;
        if (CMODE == 2) {
            a0 = poly2(s0[0]); a1 = poly2(s0[1]); a2 = poly2(s0[2]); a3 = poly2(s0[3]);
            b0 = poly2(s1[0]); b1 = poly2(s1[1]); b2 = poly2(s1[2]); b3 = poly2(s1[3]);
        } else if (CMODE == 1) {
            a0 = poly(s0[0]); a1 = poly(s0[1]); a2 = poly(s0[2]); a3 = poly(s0[3]);
            b0 = poly(s1[0]); b1 = poly(s1[1]); b2 = poly(s1[2]); b3 = poly(s1[3]);
        } else {
            const int key0 = 16 * s + (lane & 3) * 2;
            const int key8 = key0 + 8;
            a0 = poly(s0[0]); if (key0     <= relq0)     a0 += a0;
            a1 = poly(s0[1]); if (key0 + 1 <= relq0)     a1 += a1;
            a2 = poly(s0[2]); if (key0     <= relq0 + 8) a2 += a2;
            a3 = poly(s0[3]); if (key0 + 1 <= relq0 + 8) a3 += a3;
            b0 = poly(s1[0]); if (key8     <= relq0)     b0 += b0;
            b1 = poly(s1[1]); if (key8 + 1 <= relq0)     b1 += b1;
            b2 = poly(s1[2]); if (key8     <= relq0 + 8) b2 += b2;
            b3 = poly(s1[3]); if (key8 + 1 <= relq0 + 8) b3 += b3;
        }
        z0 += (a0 + a1) + (b0 + b1);
        z1 += (a2 + a3) + (b2 + b3);
        uint32_t af[4];
        af[0] = cvt2h(a0, a1);
        af[1] = cvt2h(a2, a3);
        af[2] = cvt2h(b0, b1);
        af[3] = cvt2h(b2, b3);

#pragma unroll
        for (int g4 = 0; g4 < 4; g4++) {
            uint32_t voff = sw128((uint32_t)((16 * s + ((lane >> 3) & 1) * 8 + (lane & 7)) * 128
                                             + 32 * g4 + ((lane >> 4) & 1) * 16));
            uint32_t vf[4];
            ldsm_x4t(vf, vb + voff);
            mma_f16(accY[2 * g4],     af, vf[0], vf[1]);
            mma_f16(accY[2 * g4 + 1], af, vf[2], vf[3]);
        }
    }
}

__global__ void __launch_bounds__(256, 3) attn_mma(
    const __half* __restrict__ QKf, const __half* __restrict__ Vf,
    __half* __restrict__ Yf)
{
    extern __shared__ char smem[];
    const uint32_t sb = smem_u32(smem);
    const int tid = threadIdx.x;
    const int wid = tid >> 5;
    const int lane = tid & 31;
    const int qb0 = blockIdx.x * 128;
    const int h = blockIdx.y;
    const int b = blockIdx.z;
    const size_t rowbase = (size_t)b * LSEQ;

    // prologue: G0 = Q + tile0, G1 = tile1
    {
        int r = tid >> 1, half = tid & 1;
        cp16(sb + AQ_OFF + r * 48 + half * 16,
             QKf + (rowbase + qb0 + r) * QKS + h * FEATD + half * 8);
    }
    attn_load_tile(sb, 0, 0, tid, QKf, Vf, rowbase, h);
    cp_commit();
    attn_load_tile(sb, 1, AKT, tid, QKf, Vf, rowbase, h);
    cp_commit();

    cp_wait<1>();          // G0 done: Q + tile0 ready
    __syncthreads();

    uint32_t qf[4];
    {
        uint32_t off = (uint32_t)((wid * 16 + ((lane >> 3) & 1) * 8 + (lane & 7)) * 48
                                  + ((lane >> 4) & 1) * 16);
        ldsm_x4(qf, sb + AQ_OFF + off);
    }

    float accY[8][4];
#pragma unroll
    for (int nt = 0; nt < 8; nt++)
#pragma unroll
        for (int j = 0; j < 4; j++) accY[nt][j] = 0.f;
    float z0 = 0.f, z1 = 0.f;
    const int qrow0 = qb0 + wid * 16 + (lane >> 2);

    const int NT = LSEQ / AKT;   // 32
    for (int c = 0; c < NT; c++) {
        if (c > 0) {
            cp_wait<1>();
            __syncthreads();
        }
        // issue loads for tile c+2 (writes stage (c+2)%3 == (c-1)%3)
        if (c + 2 < NT)
            attn_load_tile(sb, (c + 2) % 3, (c + 2) * AKT, tid, QKf, Vf, rowbase, h);
        cp_commit();

        const int m0 = c * AKT;
        const uint32_t kb = sb + AK_OFF + (c % 3) * 3072;
        const uint32_t vb = sb + AV_OFF + (c % 3) * 8192;
        const int relq0 = qrow0 - m0;

        if (m0 + AKT <= qb0) {
            attn_tile_body<2>(kb, vb, qf, accY, z0, z1, relq0, lane);
        } else if (m0 >= qb0 + 128) {
            attn_tile_body<1>(kb, vb, qf, accY, z0, z1, relq0, lane);
        } else {
            attn_tile_body<0>(kb, vb, qf, accY, z0, z1, relq0, lane);
        }
    }

    z0 += __shfl_xor_sync(0xFFFFFFFFu, z0, 1);
    z0 += __shfl_xor_sync(0xFFFFFFFFu, z0, 2);
    z1 += __shfl_xor_sync(0xFFFFFFFFu, z1, 1);
    z1 += __shfl_xor_sync(0xFFFFFFFFu, z1, 2);
    const float inv0 = 1.f / z0, inv1 = 1.f / z1;

    const size_t r0g = rowbase + qb0 + wid * 16 + (lane >> 2);
    const int colb = h * HD + (lane & 3) * 2;
#pragma unroll
    for (int nt = 0; nt < 8; nt++) {
        size_t o0 = r0g * DM + colb + nt * 8;
        size_t o1 = (r0g + 8) * DM + colb + nt * 8;
        *(uint32_t*)&Yf[o0] = cvt2h(accY[nt][0] * inv0, accY[nt][1] * inv0);
        *(uint32_t*)&Yf[o1] = cvt2h(accY[nt][2] * inv1, accY[nt][3] * inv1);
    }
}

// ---------------------------------------------------------------------------
extern "C" void kernel_launch(void* const* d_in, const int* in_sizes, int n_in,
                              void* d_out, int out_size)
{
    const float* hs = (const float*)d_in[0];
    const float* Wq = (const float*)d_in[1];
    const float* Wk = (const float*)d_in[2];
    const float* Wv = (const float*)d_in[3];
    const float* Wo = (const float*)d_in[4];
    float* out = (float*)d_out;

    __half *Xf, *Wf, *QKf, *Vf, *Yf, *Wof;
    cudaGetSymbolAddress((void**)&Xf, g_Xf);
    cudaGetSymbolAddress((void**)&Wf, g_Wf);
    cudaGetSymbolAddress((void**)&QKf, g_QKf);
    cudaGetSymbolAddress((void**)&Vf, g_Vf);
    cudaGetSymbolAddress((void**)&Yf, g_Yf);
    cudaGetSymbolAddress((void**)&Wof, g_Wof);

    cudaFuncSetAttribute(mma_gemm<0>, cudaFuncAttributeMaxDynamicSharedMemorySize, 3 * GSTG);
    cudaFuncSetAttribute(mma_gemm<1>, cudaFuncAttributeMaxDynamicSharedMemorySize, 3 * GSTG);
    cudaFuncSetAttribute(attn_mma, cudaFuncAttributeMaxDynamicSharedMemorySize, ASM_TOTAL);

    // Converts
    convert_h<<<(ROWS * DM) / 1024, 256>>>(hs, Xf);
    convert_weights<<<(NPROJ * DM + DM * DM) / 1024, 256>>>(Wq, Wk, Wv, Wo, Wf, Wof);

    // Merged projection
    {
        dim3 g(NPROJ / 128, ROWS / 128);
        mma_gemm<1><<<g, 256, 3 * GSTG>>>(Xf, Wf, nullptr, QKf, Vf);
    }
    // Attention
    {
        dim3 ga(LSEQ / 128, NH, BATCH);
        attn_mma<<<ga, 256, ASM_TOTAL>>>(QKf, Vf, Yf);
    }
    // Output projection
    {
        dim3 g(DM / 128, ROWS / 128);
        mma_gemm<0><<<g, 256, 3 * GSTG>>>(Yf, Wof, out, nullptr, nullptr);
    }
}

// round 16
// speedup vs baseline: 1.0243x; 1.0243x over previous
#include <cuda_runtime.h>
#include <cuda_fp16.h>
#include <cstdint>

#define LSEQ 2048
#define BATCH 2
#define NH 12
#define FEATD 16
#define HD 64
#define DM 768
#define QKS 384             // combined Q|K width
#define NPROJ 1152          // merged Q|K|V projection width
#define ROWS (BATCH * LSEQ) // 4096
#define AKT 128             // attention key tile

// Scratch (no cudaMalloc allowed)
__device__ __half g_Xf[ROWS * DM];           // X single fp16
__device__ __half g_Wf[NPROJ * DM];          // merged proj weights single fp16
__device__ __half g_QKf[ROWS * QKS];         // Q|K single fp16
__device__ __half g_Vf[ROWS * DM];           // V single fp16
__device__ __half g_Yf[ROWS * DM];           // Y single fp16
__device__ __half g_Wof[DM * DM];            // Wo single fp16

// ---- helpers ----
__device__ __forceinline__ uint32_t smem_u32(const void* p) {
    uint32_t a;
    asm("{ .reg .u64 t; cvta.to.shared.u64 t, %1; cvt.u32.u64 %0, t; }" : "=r"(a) : "l"(p));
    return a;
}
__device__ __forceinline__ uint32_t sw128(uint32_t o) { return o ^ ((o >> 3) & 0x70); }
__device__ __forceinline__ void ldsm_x4(uint32_t* r, uint32_t addr) {
    asm volatile("ldmatrix.sync.aligned.m8n8.x4.shared.b16 {%0,%1,%2,%3}, [%4];"
                 : "=r"(r[0]), "=r"(r[1]), "=r"(r[2]), "=r"(r[3]) : "r"(addr));
}
__device__ __forceinline__ void ldsm_x4t(uint32_t* r, uint32_t addr) {
    asm volatile("ldmatrix.sync.aligned.m8n8.x4.trans.shared.b16 {%0,%1,%2,%3}, [%4];"
                 : "=r"(r[0]), "=r"(r[1]), "=r"(r[2]), "=r"(r[3]) : "r"(addr));
}
__device__ __forceinline__ void mma_f16(float* d, const uint32_t* a, uint32_t b0, uint32_t b1) {
    asm volatile(
        "mma.sync.aligned.m16n8k16.row.col.f32.f16.f16.f32 "
        "{%0,%1,%2,%3}, {%4,%5,%6,%7}, {%8,%9}, {%0,%1,%2,%3};"
        : "+f"(d[0]), "+f"(d[1]), "+f"(d[2]), "+f"(d[3])
        : "r"(a[0]), "r"(a[1]), "r"(a[2]), "r"(a[3]), "r"(b0), "r"(b1));
}
__device__ __forceinline__ void cp16(uint32_t dst, const void* src) {
    asm volatile("cp.async.cg.shared.global [%0], [%1], 16;" :: "r"(dst), "l"(src));
}
__device__ __forceinline__ void cp_commit() { asm volatile("cp.async.commit_group;" ::: "memory"); }
template <int N> __device__ __forceinline__ void cp_wait() {
    asm volatile("cp.async.wait_group %0;" :: "n"(N) : "memory");
}
__device__ __forceinline__ uint32_t cvt2h(float lo, float hi) {
    uint32_t r; asm("cvt.rn.f16x2.f32 %0, %1, %2;" : "=r"(r) : "f"(hi), "f"(lo)); return r;
}
__device__ __forceinline__ float poly(float s) {      // weight-1 score
    return fmaf(s, fmaf(s, 0.03125f, 0.25f), 1.0f);
}
__device__ __forceinline__ float poly2(float s) {     // weight-2 folded in
    return fmaf(s, fmaf(s, 0.0625f, 0.5f), 2.0f);
}

// ---------------------------------------------------------------------------
// One merged converter: X + [Wq|Wk|Wv] + Wo, single launch.
// ---------------------------------------------------------------------------
#define XN (ROWS * DM)
#define WQN (192 * DM)
#define WVN (DM * DM)
__global__ void __launch_bounds__(256) convert_all(
    const float* __restrict__ hs, const float* __restrict__ Wq,
    const float* __restrict__ Wk, const float* __restrict__ Wv,
    const float* __restrict__ Wo,
    __half* __restrict__ Xf, __half* __restrict__ Wf, __half* __restrict__ Wof)
{
    int i = (blockIdx.x * 256 + threadIdx.x) * 4;
    const float* src;
    __half* dst;
    if (i < XN)                          { src = hs + i;                       dst = Xf + i; }
    else if (i < XN + WQN)               { src = Wq + (i - XN);                dst = Wf + (i - XN); }
    else if (i < XN + 2 * WQN)           { src = Wk + (i - XN - WQN);          dst = Wf + (i - XN); }
    else if (i < XN + 2 * WQN + WVN)     { src = Wv + (i - XN - 2 * WQN);      dst = Wf + (i - XN); }
    else                                 { src = Wo + (i - XN - 2 * WQN - WVN); dst = Wof + (i - XN - 2 * WQN - WVN); }
    float4 v = *(const float4*)src;
    ((uint32_t*)dst)[0] = cvt2h(v.x, v.y);
    ((uint32_t*)dst)[1] = cvt2h(v.z, v.w);
}

// ---------------------------------------------------------------------------
// Single-pass fp16 GEMM (R12 shape): C[M,N] = A[M,768] @ B[N,768]^T
// CTA 128x128, 8 warps (4x2), warp 32x64, BK=64, 2-stage cp.async, occ 2.
// MODE 0: fp32 out (outproj). MODE 1: proj epilogue (QKf / Vf split by col).
// ---------------------------------------------------------------------------
#define GSTG 32768
#define G_A 0
#define G_B 16384

template <int MODE>
__global__ void __launch_bounds__(256, 2) mma_gemm(
    const __half* __restrict__ A, const __half* __restrict__ B,
    float* __restrict__ C, __half* __restrict__ QKf, __half* __restrict__ Vf)
{
    extern __shared__ char smem[];
    const uint32_t sb = smem_u32(smem);
    const int tid = threadIdx.x;
    const int wid = tid >> 5;
    const int lane = tid & 31;
    const int warpRow = wid >> 1;
    const int warpCol = wid & 1;
    const int m0 = blockIdx.y * 128;
    const int n0 = blockIdx.x * 128;

    const int lrow8 = ((lane >> 3) & 1) * 8 + (lane & 7);
    const int klane = ((lane >> 4) & 1) * 16;
    const int a_row = warpRow * 32 + lrow8;
    const int b_row = warpCol * 64 + lrow8;

    float acc[2][8][4];
#pragma unroll
    for (int mt = 0; mt < 2; mt++)
#pragma unroll
        for (int nt = 0; nt < 8; nt++)
#pragma unroll
            for (int j = 0; j < 4; j++) acc[mt][nt][j] = 0.f;

    const int NCH = DM / 64;
    {
#pragma unroll
        for (int t = 0; t < 4; t++) {
            int u = tid + t * 256;
            int r = u >> 3, cb = (u & 7) * 16;
            uint32_t sw = sw128((uint32_t)(r * 128 + cb));
            cp16(sb + G_A + sw, A + (size_t)(m0 + r) * DM + (cb >> 1));
            cp16(sb + G_B + sw, B + (size_t)(n0 + r) * DM + (cb >> 1));
        }
        cp_commit();
    }

    for (int c = 0; c < NCH; c++) {
        if (c + 1 < NCH) {
            uint32_t s1 = sb + ((c + 1) & 1) * GSTG;
            int k0 = (c + 1) * 64;
#pragma unroll
            for (int t = 0; t < 4; t++) {
                int u = tid + t * 256;
                int r = u >> 3, cb = (u & 7) * 16;
                uint32_t sw = sw128((uint32_t)(r * 128 + cb));
                cp16(s1 + G_A + sw, A + (size_t)(m0 + r) * DM + k0 + (cb >> 1));
                cp16(s1 + G_B + sw, B + (size_t)(n0 + r) * DM + k0 + (cb >> 1));
            }
            cp_commit();
            cp_wait<1>();
        } else {
            cp_wait<0>();
        }
        __syncthreads();

        const uint32_t sc = sb + (c & 1) * GSTG;
#pragma unroll
        for (int kt = 0; kt < 4; kt++) {
            const uint32_t kb = kt * 32 + klane;
            uint32_t a[2][4], b[4][4];
#pragma unroll
            for (int mt = 0; mt < 2; mt++)
                ldsm_x4(a[mt], sc + G_A + sw128((uint32_t)((a_row + mt * 16) * 128 + kb)));
#pragma unroll
            for (int nt2 = 0; nt2 < 4; nt2++)
                ldsm_x4(b[nt2], sc + G_B + sw128((uint32_t)((b_row + nt2 * 16) * 128 + kb)));
#pragma unroll
            for (int mt = 0; mt < 2; mt++)
#pragma unroll
                for (int nt = 0; nt < 8; nt++) {
                    int p = nt >> 1, j = nt & 1;
                    mma_f16(acc[mt][nt], a[mt], b[p][j], b[p][2 + j]);
                }
        }
        __syncthreads();
    }

    const int g = lane >> 2;
    const int tc = (lane & 3) * 2;
#pragma unroll
    for (int mt = 0; mt < 2; mt++) {
        int row = m0 + warpRow * 32 + mt * 16 + g;
#pragma unroll
        for (int nt = 0; nt < 8; nt++) {
            int col = n0 + warpCol * 64 + nt * 8 + tc;
            float v0 = acc[mt][nt][0], v1 = acc[mt][nt][1];
            float v2 = acc[mt][nt][2], v3 = acc[mt][nt][3];
            if (MODE == 0) {
                *(float2*)&C[(size_t)row * DM + col] = make_float2(v0, v1);
                *(float2*)&C[(size_t)(row + 8) * DM + col] = make_float2(v2, v3);
            } else {
                if (col < QKS) {
                    *(uint32_t*)&QKf[(size_t)row * QKS + col] = cvt2h(v0, v1);
                    *(uint32_t*)&QKf[(size_t)(row + 8) * QKS + col] = cvt2h(v2, v3);
                } else {
                    int c2 = col - QKS;
                    *(uint32_t*)&Vf[(size_t)row * DM + c2] = cvt2h(v0, v1);
                    *(uint32_t*)&Vf[(size_t)(row + 8) * DM + c2] = cvt2h(v2, v3);
                }
            }
        }
    }
}

// ---------------------------------------------------------------------------
// HMMA attention (R12 pipeline, AKT=128): 8 warps x 16 query rows.
// S fp16 1-pass; A fp16; AV fp16 1-pass; z fp32 exact.
// Causal modes: 2 = all weight-2 (poly2), 1 = all weight-1, 0 = mixed.
// ---------------------------------------------------------------------------
#define AQ_OFF 0                       // 128 rows * 48B = 6144
#define AK_OFF 6144                    // + st*6144  (2 stages, 128 rows * 48B)
#define AV_OFF 18432                   // + st*16384 (2 stages, 128 rows * 128B)
#define ASM_TOTAL 51200

__device__ __forceinline__ void attn_load_tile(
    uint32_t sb, int st, int m0, int tid,
    const __half* QKf, const __half* Vf, size_t rowbase, int h)
{
    // K: 128 rows x 32B, pitch 48B
    {
        int r = tid >> 1, half = tid & 1;
        cp16(sb + AK_OFF + st * 6144 + r * 48 + half * 16,
             QKf + (rowbase + m0 + r) * QKS + 192 + h * FEATD + half * 8);
    }
    // V: 128 rows x 128B, SW128
#pragma unroll
    for (int i = 0; i < 4; i++) {
        int u = tid + i * 256;
        int r = u >> 3, ch = (u & 7) * 16;
        cp16(sb + AV_OFF + st * 16384 + sw128((uint32_t)(r * 128 + ch)),
             Vf + (rowbase + m0 + r) * DM + h * HD + (ch >> 1));
    }
}

template <int CMODE>
__device__ __forceinline__ void attn_tile_body(
    uint32_t kb, uint32_t vb, const uint32_t* qf,
    float accY[8][4], float& z0, float& z1, int relq0, int lane)
{
#pragma unroll
    for (int s = 0; s < 8; s++) {
        uint32_t koff = (uint32_t)((16 * s + ((lane >> 4) & 1) * 8 + (lane & 7)) * 48
                                   + ((lane >> 3) & 1) * 16);
        uint32_t bf[4];
        ldsm_x4(bf, kb + koff);
        float s0[4] = {0.f, 0.f, 0.f, 0.f};
        float s1[4] = {0.f, 0.f, 0.f, 0.f};
        mma_f16(s0, qf, bf[0], bf[1]);
        mma_f16(s1, qf, bf[2], bf[3]);

        float a0, a1, a2, a3, b0, b1, b2, b3;
        if (CMODE == 2) {
            a0 = poly2(s0[0]); a1 = poly2(s0[1]); a2 = poly2(s0[2]); a3 = poly2(s0[3]);
            b0 = poly2(s1[0]); b1 = poly2(s1[1]); b2 = poly2(s1[2]); b3 = poly2(s1[3]);
        } else if (CMODE == 1) {
            a0 = poly(s0[0]); a1 = poly(s0[1]); a2 = poly(s0[2]); a3 = poly(s0[3]);
            b0 = poly(s1[0]); b1 = poly(s1[1]); b2 = poly(s1[2]); b3 = poly(s1[3]);
        } else {
            const int key0 = 16 * s + (lane & 3) * 2;
            const int key8 = key0 + 8;
            a0 = poly(s0[0]); if (key0     <= relq0)     a0 += a0;
            a1 = poly(s0[1]); if (key0 + 1 <= relq0)     a1 += a1;
            a2 = poly(s0[2]); if (key0     <= relq0 + 8) a2 += a2;
            a3 = poly(s0[3]); if (key0 + 1 <= relq0 + 8) a3 += a3;
            b0 = poly(s1[0]); if (key8     <= relq0)     b0 += b0;
            b1 = poly(s1[1]); if (key8 + 1 <= relq0)     b1 += b1;
            b2 = poly(s1[2]); if (key8     <= relq0 + 8) b2 += b2;
            b3 = poly(s1[3]); if (key8 + 1 <= relq0 + 8) b3 += b3;
        }
        z0 += (a0 + a1) + (b0 + b1);
        z1 += (a2 + a3) + (b2 + b3);
        uint32_t af[4];
        af[0] = cvt2h(a0, a1);
        af[1] = cvt2h(a2, a3);
        af[2] = cvt2h(b0, b1);
        af[3] = cvt2h(b2, b3);

#pragma unroll
        for (int g4 = 0; g4 < 4; g4++) {
            uint32_t voff = sw128((uint32_t)((16 * s + ((lane >> 3) & 1) * 8 + (lane & 7)) * 128
                                             + 32 * g4 + ((lane >> 4) & 1) * 16));
            uint32_t vf[4];
            ldsm_x4t(vf, vb + voff);
            mma_f16(accY[2 * g4],     af, vf[0], vf[1]);
            mma_f16(accY[2 * g4 + 1], af, vf[2], vf[3]);
        }
    }
}

__global__ void __launch_bounds__(256, 3) attn_mma(
    const __half* __restrict__ QKf, const __half* __restrict__ Vf,
    __half* __restrict__ Yf)
{
    extern __shared__ char smem[];
    const uint32_t sb = smem_u32(smem);
    const int tid = threadIdx.x;
    const int wid = tid >> 5;
    const int lane = tid & 31;
    const int qb0 = blockIdx.x * 128;
    const int h = blockIdx.y;
    const int b = blockIdx.z;
    const size_t rowbase = (size_t)b * LSEQ;

    // group 0: Q
    {
        int r = tid >> 1, half = tid & 1;
        cp16(sb + AQ_OFF + r * 48 + half * 16,
             QKf + (rowbase + qb0 + r) * QKS + h * FEATD + half * 8);
    }
    cp_commit();
    // group 1: tile 0
    attn_load_tile(sb, 0, 0, tid, QKf, Vf, rowbase, h);
    cp_commit();
    cp_wait<1>();           // Q ready
    __syncthreads();

    uint32_t qf[4];
    {
        uint32_t off = (uint32_t)((wid * 16 + ((lane >> 3) & 1) * 8 + (lane & 7)) * 48
                                  + ((lane >> 4) & 1) * 16);
        ldsm_x4(qf, sb + AQ_OFF + off);
    }

    float accY[8][4];
#pragma unroll
    for (int nt = 0; nt < 8; nt++)
#pragma unroll
        for (int j = 0; j < 4; j++) accY[nt][j] = 0.f;
    float z0 = 0.f, z1 = 0.f;
    const int qrow0 = qb0 + wid * 16 + (lane >> 2);

    const int NT = LSEQ / AKT;   // 16
    for (int c = 0; c < NT; c++) {
        const int m0 = c * AKT;
        if (c + 1 < NT) {
            attn_load_tile(sb, (c + 1) & 1, m0 + AKT, tid, QKf, Vf, rowbase, h);
            cp_commit();
            cp_wait<1>();
        } else {
            cp_wait<0>();
        }
        __syncthreads();

        const uint32_t kb = sb + AK_OFF + (c & 1) * 6144;
        const uint32_t vb = sb + AV_OFF + (c & 1) * 16384;
        const int relq0 = qrow0 - m0;

        if (m0 + AKT <= qb0) {
            attn_tile_body<2>(kb, vb, qf, accY, z0, z1, relq0, lane);
        } else if (m0 >= qb0 + 128) {
            attn_tile_body<1>(kb, vb, qf, accY, z0, z1, relq0, lane);
        } else {
            attn_tile_body<0>(kb, vb, qf, accY, z0, z1, relq0, lane);
        }
        __syncthreads();
    }

    z0 += __shfl_xor_sync(0xFFFFFFFFu, z0, 1);
    z0 += __shfl_xor_sync(0xFFFFFFFFu, z0, 2);
    z1 += __shfl_xor_sync(0xFFFFFFFFu, z1, 1);
    z1 += __shfl_xor_sync(0xFFFFFFFFu, z1, 2);
    const float inv0 = 1.f / z0, inv1 = 1.f / z1;

    const size_t r0g = rowbase + qb0 + wid * 16 + (lane >> 2);
    const int colb = h * HD + (lane & 3) * 2;
#pragma unroll
    for (int nt = 0; nt < 8; nt++) {
        size_t o0 = r0g * DM + colb + nt * 8;
        size_t o1 = (r0g + 8) * DM + colb + nt * 8;
        *(uint32_t*)&Yf[o0] = cvt2h(accY[nt][0] * inv0, accY[nt][1] * inv0);
        *(uint32_t*)&Yf[o1] = cvt2h(accY[nt][2] * inv1, accY[nt][3] * inv1);
    }
}

// ---------------------------------------------------------------------------
extern "C" void kernel_launch(void* const* d_in, const int* in_sizes, int n_in,
                              void* d_out, int out_size)
{
    const float* hs = (const float*)d_in[0];
    const float* Wq = (const float*)d_in[1];
    const float* Wk = (const float*)d_in[2];
    const float* Wv = (const float*)d_in[3];
    const float* Wo = (const float*)d_in[4];
    float* out = (float*)d_out;

    __half *Xf, *Wf, *QKf, *Vf, *Yf, *Wof;
    cudaGetSymbolAddress((void**)&Xf, g_Xf);
    cudaGetSymbolAddress((void**)&Wf, g_Wf);
    cudaGetSymbolAddress((void**)&QKf, g_QKf);
    cudaGetSymbolAddress((void**)&Vf, g_Vf);
    cudaGetSymbolAddress((void**)&Yf, g_Yf);
    cudaGetSymbolAddress((void**)&Wof, g_Wof);

    cudaFuncSetAttribute(mma_gemm<0>, cudaFuncAttributeMaxDynamicSharedMemorySize, 2 * GSTG);
    cudaFuncSetAttribute(mma_gemm<1>, cudaFuncAttributeMaxDynamicSharedMemorySize, 2 * GSTG);
    cudaFuncSetAttribute(attn_mma, cudaFuncAttributeMaxDynamicSharedMemorySize, ASM_TOTAL);

    // All converts in one launch
    convert_all<<<(XN + NPROJ * DM + DM * DM) / 1024, 256>>>(
        hs, Wq, Wk, Wv, Wo, Xf, Wf, Wof);

    // Merged projection
    {
        dim3 g(NPROJ / 128, ROWS / 128);
        mma_gemm<1><<<g, 256, 2 * GSTG>>>(Xf, Wf, nullptr, QKf, Vf);
    }
    // Attention (AKT=128)
    {
        dim3 ga(LSEQ / 128, NH, BATCH);
        attn_mma<<<ga, 256, ASM_TOTAL>>>(QKf, Vf, Yf);
    }
    // Output projection
    {
        dim3 g(DM / 128, ROWS / 128);
        mma_gemm<0><<<g, 256, 2 * GSTG>>>(Yf, Wof, out, nullptr, nullptr);
    }
}

// round 17
// speedup vs baseline: 1.0781x; 1.0525x over previous
#include <cuda_runtime.h>
#include <cuda_fp16.h>
#include <cstdint>

#define LSEQ 2048
#define BATCH 2
#define NH 12
#define FEATD 16
#define HD 64
#define DM 768
#define QKS 384             // combined Q|K width
#define NPROJ 1152          // merged Q|K|V projection width
#define ROWS (BATCH * LSEQ) // 4096
#define AKT 64              // attention key tile

// Scratch (no cudaMalloc allowed)
__device__ __half g_Xf[ROWS * DM];           // X single fp16
__device__ __half g_Wf[NPROJ * DM];          // merged proj weights single fp16
__device__ __half g_QKf[ROWS * QKS];         // Q|K single fp16
__device__ __half g_Vf[ROWS * DM];           // V single fp16
__device__ __half g_Yf[ROWS * DM];           // Y single fp16
__device__ __half g_Wof[DM * DM];            // Wo single fp16

// ---- helpers ----
__device__ __forceinline__ uint32_t smem_u32(const void* p) {
    uint32_t a;
    asm("{ .reg .u64 t; cvta.to.shared.u64 t, %1; cvt.u32.u64 %0, t; }" : "=r"(a) : "l"(p));
    return a;
}
__device__ __forceinline__ uint32_t sw128(uint32_t o) { return o ^ ((o >> 3) & 0x70); }
__device__ __forceinline__ void ldsm_x4(uint32_t* r, uint32_t addr) {
    asm volatile("ldmatrix.sync.aligned.m8n8.x4.shared.b16 {%0,%1,%2,%3}, [%4];"
                 : "=r"(r[0]), "=r"(r[1]), "=r"(r[2]), "=r"(r[3]) : "r"(addr));
}
__device__ __forceinline__ void ldsm_x4t(uint32_t* r, uint32_t addr) {
    asm volatile("ldmatrix.sync.aligned.m8n8.x4.trans.shared.b16 {%0,%1,%2,%3}, [%4];"
                 : "=r"(r[0]), "=r"(r[1]), "=r"(r[2]), "=r"(r[3]) : "r"(addr));
}
__device__ __forceinline__ void mma_f16(float* d, const uint32_t* a, uint32_t b0, uint32_t b1) {
    asm volatile(
        "mma.sync.aligned.m16n8k16.row.col.f32.f16.f16.f32 "
        "{%0,%1,%2,%3}, {%4,%5,%6,%7}, {%8,%9}, {%0,%1,%2,%3};"
        : "+f"(d[0]), "+f"(d[1]), "+f"(d[2]), "+f"(d[3])
        : "r"(a[0]), "r"(a[1]), "r"(a[2]), "r"(a[3]), "r"(b0), "r"(b1));
}
__device__ __forceinline__ void cp16(uint32_t dst, const void* src) {
    asm volatile("cp.async.cg.shared.global [%0], [%1], 16;" :: "r"(dst), "l"(src));
}
__device__ __forceinline__ void cp_commit() { asm volatile("cp.async.commit_group;" ::: "memory"); }
template <int N> __device__ __forceinline__ void cp_wait() {
    asm volatile("cp.async.wait_group %0;" :: "n"(N) : "memory");
}
__device__ __forceinline__ uint32_t cvt2h(float lo, float hi) {
    uint32_t r; asm("cvt.rn.f16x2.f32 %0, %1, %2;" : "=r"(r) : "f"(hi), "f"(lo)); return r;
}
__device__ __forceinline__ float poly(float s) {      // weight-1 score
    return fmaf(s, fmaf(s, 0.03125f, 0.25f), 1.0f);
}
__device__ __forceinline__ float poly2(float s) {     // weight-2 folded in
    return fmaf(s, fmaf(s, 0.0625f, 0.5f), 2.0f);
}

// ---------------------------------------------------------------------------
// One merged converter: X + [Wq|Wk|Wv] + Wo, single launch.
// ---------------------------------------------------------------------------
#define XN (ROWS * DM)
#define WQN (192 * DM)
#define WVN (DM * DM)
__global__ void __launch_bounds__(256) convert_all(
    const float* __restrict__ hs, const float* __restrict__ Wq,
    const float* __restrict__ Wk, const float* __restrict__ Wv,
    const float* __restrict__ Wo,
    __half* __restrict__ Xf, __half* __restrict__ Wf, __half* __restrict__ Wof)
{
    int i = (blockIdx.x * 256 + threadIdx.x) * 4;
    const float* src;
    __half* dst;
    if (i < XN)                          { src = hs + i;                       dst = Xf + i; }
    else if (i < XN + WQN)               { src = Wq + (i - XN);                dst = Wf + (i - XN); }
    else if (i < XN + 2 * WQN)           { src = Wk + (i - XN - WQN);          dst = Wf + (i - XN); }
    else if (i < XN + 2 * WQN + WVN)     { src = Wv + (i - XN - 2 * WQN);      dst = Wf + (i - XN); }
    else                                 { src = Wo + (i - XN - 2 * WQN - WVN); dst = Wof + (i - XN - 2 * WQN - WVN); }
    float4 v = *(const float4*)src;
    ((uint32_t*)dst)[0] = cvt2h(v.x, v.y);
    ((uint32_t*)dst)[1] = cvt2h(v.z, v.w);
}

// ---------------------------------------------------------------------------
// Projection GEMM (R12 shape): [QK|V] = X @ Wf^T.
// CTA 128x128, 8 warps (4x2), warp 32x64, BK=64, 2-stage, occ 2.
// ---------------------------------------------------------------------------
#define GSTG 32768
#define G_A 0
#define G_B 16384

__global__ void __launch_bounds__(256, 2) mma_proj(
    const __half* __restrict__ A, const __half* __restrict__ B,
    __half* __restrict__ QKf, __half* __restrict__ Vf)
{
    extern __shared__ char smem[];
    const uint32_t sb = smem_u32(smem);
    const int tid = threadIdx.x;
    const int wid = tid >> 5;
    const int lane = tid & 31;
    const int warpRow = wid >> 1;
    const int warpCol = wid & 1;
    const int m0 = blockIdx.y * 128;
    const int n0 = blockIdx.x * 128;

    const int lrow8 = ((lane >> 3) & 1) * 8 + (lane & 7);
    const int klane = ((lane >> 4) & 1) * 16;
    const int a_row = warpRow * 32 + lrow8;
    const int b_row = warpCol * 64 + lrow8;

    float acc[2][8][4];
#pragma unroll
    for (int mt = 0; mt < 2; mt++)
#pragma unroll
        for (int nt = 0; nt < 8; nt++)
#pragma unroll
            for (int j = 0; j < 4; j++) acc[mt][nt][j] = 0.f;

    const int NCH = DM / 64;
    {
#pragma unroll
        for (int t = 0; t < 4; t++) {
            int u = tid + t * 256;
            int r = u >> 3, cb = (u & 7) * 16;
            uint32_t sw = sw128((uint32_t)(r * 128 + cb));
            cp16(sb + G_A + sw, A + (size_t)(m0 + r) * DM + (cb >> 1));
            cp16(sb + G_B + sw, B + (size_t)(n0 + r) * DM + (cb >> 1));
        }
        cp_commit();
    }

    for (int c = 0; c < NCH; c++) {
        if (c + 1 < NCH) {
            uint32_t s1 = sb + ((c + 1) & 1) * GSTG;
            int k0 = (c + 1) * 64;
#pragma unroll
            for (int t = 0; t < 4; t++) {
                int u = tid + t * 256;
                int r = u >> 3, cb = (u & 7) * 16;
                uint32_t sw = sw128((uint32_t)(r * 128 + cb));
                cp16(s1 + G_A + sw, A + (size_t)(m0 + r) * DM + k0 + (cb >> 1));
                cp16(s1 + G_B + sw, B + (size_t)(n0 + r) * DM + k0 + (cb >> 1));
            }
            cp_commit();
            cp_wait<1>();
        } else {
            cp_wait<0>();
        }
        __syncthreads();

        const uint32_t sc = sb + (c & 1) * GSTG;
#pragma unroll
        for (int kt = 0; kt < 4; kt++) {
            const uint32_t kb = kt * 32 + klane;
            uint32_t a[2][4], b[4][4];
#pragma unroll
            for (int mt = 0; mt < 2; mt++)
                ldsm_x4(a[mt], sc + G_A + sw128((uint32_t)((a_row + mt * 16) * 128 + kb)));
#pragma unroll
            for (int nt2 = 0; nt2 < 4; nt2++)
                ldsm_x4(b[nt2], sc + G_B + sw128((uint32_t)((b_row + nt2 * 16) * 128 + kb)));
#pragma unroll
            for (int mt = 0; mt < 2; mt++)
#pragma unroll
                for (int nt = 0; nt < 8; nt++) {
                    int p = nt >> 1, j = nt & 1;
                    mma_f16(acc[mt][nt], a[mt], b[p][j], b[p][2 + j]);
                }
        }
        __syncthreads();
    }

    const int g = lane >> 2;
    const int tc = (lane & 3) * 2;
#pragma unroll
    for (int mt = 0; mt < 2; mt++) {
        int row = m0 + warpRow * 32 + mt * 16 + g;
#pragma unroll
        for (int nt = 0; nt < 8; nt++) {
            int col = n0 + warpCol * 64 + nt * 8 + tc;
            float v0 = acc[mt][nt][0], v1 = acc[mt][nt][1];
            float v2 = acc[mt][nt][2], v3 = acc[mt][nt][3];
            if (col < QKS) {
                *(uint32_t*)&QKf[(size_t)row * QKS + col] = cvt2h(v0, v1);
                *(uint32_t*)&QKf[(size_t)(row + 8) * QKS + col] = cvt2h(v2, v3);
            } else {
                int c2 = col - QKS;
                *(uint32_t*)&Vf[(size_t)row * DM + c2] = cvt2h(v0, v1);
                *(uint32_t*)&Vf[(size_t)(row + 8) * DM + c2] = cvt2h(v2, v3);
            }
        }
    }
}

// ---------------------------------------------------------------------------
// Output projection GEMM (R11 shape): out[fp32] = Yf @ Wof^T.
// CTA 128x64, 8 warps (4x2), warp 32x32, BK=64, 2-stage, occ 4.
// Grid 384 CTAs -> 592 slots, strong latency hiding for this small GEMM.
// ---------------------------------------------------------------------------
#define OSTG 24576
#define O_A 0
#define O_B 16384

__global__ void __launch_bounds__(256, 4) mma_out64(
    const __half* __restrict__ A, const __half* __restrict__ B,
    float* __restrict__ C)
{
    extern __shared__ char smem[];
    const uint32_t sb = smem_u32(smem);
    const int tid = threadIdx.x;
    const int wid = tid >> 5;
    const int lane = tid & 31;
    const int warpRow = wid >> 1;
    const int warpCol = wid & 1;
    const int m0 = blockIdx.y * 128;
    const int n0 = blockIdx.x * 64;

    const int lrow8 = ((lane >> 3) & 1) * 8 + (lane & 7);
    const int klane = ((lane >> 4) & 1) * 16;
    const int a_row = warpRow * 32 + lrow8;
    const int b_row = warpCol * 32 + lrow8;

    float acc[2][4][4];
#pragma unroll
    for (int mt = 0; mt < 2; mt++)
#pragma unroll
        for (int nt = 0; nt < 4; nt++)
#pragma unroll
            for (int j = 0; j < 4; j++) acc[mt][nt][j] = 0.f;

    const int NCH = DM / 64;
    {
#pragma unroll
        for (int t = 0; t < 4; t++) {
            int u = tid + t * 256;
            int r = u >> 3, cb = (u & 7) * 16;
            cp16(sb + O_A + sw128((uint32_t)(r * 128 + cb)),
                 A + (size_t)(m0 + r) * DM + (cb >> 1));
        }
#pragma unroll
        for (int t = 0; t < 2; t++) {
            int u = tid + t * 256;
            int r = u >> 3, cb = (u & 7) * 16;
            cp16(sb + O_B + sw128((uint32_t)(r * 128 + cb)),
                 B + (size_t)(n0 + r) * DM + (cb >> 1));
        }
        cp_commit();
    }

    for (int c = 0; c < NCH; c++) {
        if (c + 1 < NCH) {
            uint32_t s1 = sb + ((c + 1) & 1) * OSTG;
            int k0 = (c + 1) * 64;
#pragma unroll
            for (int t = 0; t < 4; t++) {
                int u = tid + t * 256;
                int r = u >> 3, cb = (u & 7) * 16;
                cp16(s1 + O_A + sw128((uint32_t)(r * 128 + cb)),
                     A + (size_t)(m0 + r) * DM + k0 + (cb >> 1));
            }
#pragma unroll
            for (int t = 0; t < 2; t++) {
                int u = tid + t * 256;
                int r = u >> 3, cb = (u & 7) * 16;
                cp16(s1 + O_B + sw128((uint32_t)(r * 128 + cb)),
                     B + (size_t)(n0 + r) * DM + k0 + (cb >> 1));
            }
            cp_commit();
            cp_wait<1>();
        } else {
            cp_wait<0>();
        }
        __syncthreads();

        const uint32_t sc = sb + (c & 1) * OSTG;
#pragma unroll
        for (int kt = 0; kt < 4; kt++) {
            const uint32_t kb = kt * 32 + klane;
            uint32_t a[2][4], b[2][4];
#pragma unroll
            for (int mt = 0; mt < 2; mt++)
                ldsm_x4(a[mt], sc + O_A + sw128((uint32_t)((a_row + mt * 16) * 128 + kb)));
#pragma unroll
            for (int nt2 = 0; nt2 < 2; nt2++)
                ldsm_x4(b[nt2], sc + O_B + sw128((uint32_t)((b_row + nt2 * 16) * 128 + kb)));
#pragma unroll
            for (int mt = 0; mt < 2; mt++)
#pragma unroll
                for (int nt = 0; nt < 4; nt++) {
                    int p = nt >> 1, j = nt & 1;
                    mma_f16(acc[mt][nt], a[mt], b[p][j], b[p][2 + j]);
                }
        }
        __syncthreads();
    }

    const int g = lane >> 2;
    const int tc = (lane & 3) * 2;
#pragma unroll
    for (int mt = 0; mt < 2; mt++) {
        int row = m0 + warpRow * 32 + mt * 16 + g;
#pragma unroll
        for (int nt = 0; nt < 4; nt++) {
            int col = n0 + warpCol * 32 + nt * 8 + tc;
            *(float2*)&C[(size_t)row * DM + col] =
                make_float2(acc[mt][nt][0], acc[mt][nt][1]);
            *(float2*)&C[(size_t)(row + 8) * DM + col] =
                make_float2(acc[mt][nt][2], acc[mt][nt][3]);
        }
    }
}

// ---------------------------------------------------------------------------
// HMMA attention (exact R12): 8 warps x 16 query rows, AKT=64, occ 3.
// S fp16 1-pass; A fp16; AV fp16 1-pass; z fp32 exact.
// ---------------------------------------------------------------------------
#define AQ_OFF 0                       // 128 rows * 48B = 6144
#define AK_OFF 6144                    // + st*3072
#define AV_OFF 12288                   // + st*8192
#define ASM_TOTAL 28672

__device__ __forceinline__ void attn_load_tile(
    uint32_t sb, int st, int m0, int tid,
    const __half* QKf, const __half* Vf, size_t rowbase, int h)
{
    if (tid < 128) {
        int r = tid >> 1, half = tid & 1;
        cp16(sb + AK_OFF + st * 3072 + r * 48 + half * 16,
             QKf + (rowbase + m0 + r) * QKS + 192 + h * FEATD + half * 8);
    }
#pragma unroll
    for (int i = 0; i < 2; i++) {
        int u = tid + i * 256;
        int r = u >> 3, ch = (u & 7) * 16;
        cp16(sb + AV_OFF + st * 8192 + sw128((uint32_t)(r * 128 + ch)),
             Vf + (rowbase + m0 + r) * DM + h * HD + (ch >> 1));
    }
}

template <int CMODE>
__device__ __forceinline__ void attn_tile_body(
    uint32_t kb, uint32_t vb, const uint32_t* qf,
    float accY[8][4], float& z0, float& z1, int relq0, int lane)
{
#pragma unroll
    for (int s = 0; s < 4; s++) {
        uint32_t koff = (uint32_t)((16 * s + ((lane >> 4) & 1) * 8 + (lane & 7)) * 48
                                   + ((lane >> 3) & 1) * 16);
        uint32_t bf[4];
        ldsm_x4(bf, kb + koff);
        float s0[4] = {0.f, 0.f, 0.f, 0.f};
        float s1[4] = {0.f, 0.f, 0.f, 0.f};
        mma_f16(s0, qf, bf[0], bf[1]);
        mma_f16(s1, qf, bf[2], bf[3]);

        float a0, a1, a2, a3, b0, b1, b2, b3;
        if (CMODE == 2) {
            a0 = poly2(s0[0]); a1 = poly2(s0[1]); a2 = poly2(s0[2]); a3 = poly2(s0[3]);
            b0 = poly2(s1[0]); b1 = poly2(s1[1]); b2 = poly2(s1[2]); b3 = poly2(s1[3]);
        } else if (CMODE == 1) {
            a0 = poly(s0[0]); a1 = poly(s0[1]); a2 = poly(s0[2]); a3 = poly(s0[3]);
            b0 = poly(s1[0]); b1 = poly(s1[1]); b2 = poly(s1[2]); b3 = poly(s1[3]);
        } else {
            const int key0 = 16 * s + (lane & 3) * 2;
            const int key8 = key0 + 8;
            a0 = poly(s0[0]); if (key0     <= relq0)     a0 += a0;
            a1 = poly(s0[1]); if (key0 + 1 <= relq0)     a1 += a1;
            a2 = poly(s0[2]); if (key0     <= relq0 + 8) a2 += a2;
            a3 = poly(s0[3]); if (key0 + 1 <= relq0 + 8) a3 += a3;
            b0 = poly(s1[0]); if (key8     <= relq0)     b0 += b0;
            b1 = poly(s1[1]); if (key8 + 1 <= relq0)     b1 += b1;
            b2 = poly(s1[2]); if (key8     <= relq0 + 8) b2 += b2;
            b3 = poly(s1[3]); if (key8 + 1 <= relq0 + 8) b3 += b3;
        }
        z0 += (a0 + a1) + (b0 + b1);
        z1 += (a2 + a3) + (b2 + b3);
        uint32_t af[4];
        af[0] = cvt2h(a0, a1);
        af[1] = cvt2h(a2, a3);
        af[2] = cvt2h(b0, b1);
        af[3] = cvt2h(b2, b3);

#pragma unroll
        for (int g4 = 0; g4 < 4; g4++) {
            uint32_t voff = sw128((uint32_t)((16 * s + ((lane >> 3) & 1) * 8 + (lane & 7)) * 128
                                             + 32 * g4 + ((lane >> 4) & 1) * 16));
            uint32_t vf[4];
            ldsm_x4t(vf, vb + voff);
            mma_f16(accY[2 * g4],     af, vf[0], vf[1]);
            mma_f16(accY[2 * g4 + 1], af, vf[2], vf[3]);
        }
    }
}

__global__ void __launch_bounds__(256, 3) attn_mma(
    const __half* __restrict__ QKf, const __half* __restrict__ Vf,
    __half* __restrict__ Yf)
{
    extern __shared__ char smem[];
    const uint32_t sb = smem_u32(smem);
    const int tid = threadIdx.x;
    const int wid = tid >> 5;
    const int lane = tid & 31;
    const int qb0 = blockIdx.x * 128;
    const int h = blockIdx.y;
    const int b = blockIdx.z;
    const size_t rowbase = (size_t)b * LSEQ;

    {
        int r = tid >> 1, half = tid & 1;
        cp16(sb + AQ_OFF + r * 48 + half * 16,
             QKf + (rowbase + qb0 + r) * QKS + h * FEATD + half * 8);
    }
    cp_commit();
    attn_load_tile(sb, 0, 0, tid, QKf, Vf, rowbase, h);
    cp_commit();
    cp_wait<1>();
    __syncthreads();

    uint32_t qf[4];
    {
        uint32_t off = (uint32_t)((wid * 16 + ((lane >> 3) & 1) * 8 + (lane & 7)) * 48
                                  + ((lane >> 4) & 1) * 16);
        ldsm_x4(qf, sb + AQ_OFF + off);
    }

    float accY[8][4];
#pragma unroll
    for (int nt = 0; nt < 8; nt++)
#pragma unroll
        for (int j = 0; j < 4; j++) accY[nt][j] = 0.f;
    float z0 = 0.f, z1 = 0.f;
    const int qrow0 = qb0 + wid * 16 + (lane >> 2);

    const int NT = LSEQ / AKT;
    for (int c = 0; c < NT; c++) {
        const int m0 = c * AKT;
        if (c + 1 < NT) {
            attn_load_tile(sb, (c + 1) & 1, m0 + AKT, tid, QKf, Vf, rowbase, h);
            cp_commit();
            cp_wait<1>();
        } else {
            cp_wait<0>();
        }
        __syncthreads();

        const uint32_t kb = sb + AK_OFF + (c & 1) * 3072;
        const uint32_t vb = sb + AV_OFF + (c & 1) * 8192;
        const int relq0 = qrow0 - m0;

        if (m0 + AKT <= qb0) {
            attn_tile_body<2>(kb, vb, qf, accY, z0, z1, relq0, lane);
        } else if (m0 >= qb0 + 128) {
            attn_tile_body<1>(kb, vb, qf, accY, z0, z1, relq0, lane);
        } else {
            attn_tile_body<0>(kb, vb, qf, accY, z0, z1, relq0, lane);
        }
        __syncthreads();
    }

    z0 += __shfl_xor_sync(0xFFFFFFFFu, z0, 1);
    z0 += __shfl_xor_sync(0xFFFFFFFFu, z0, 2);
    z1 += __shfl_xor_sync(0xFFFFFFFFu, z1, 1);
    z1 += __shfl_xor_sync(0xFFFFFFFFu, z1, 2);
    const float inv0 = 1.f / z0, inv1 = 1.f / z1;

    const size_t r0g = rowbase + qb0 + wid * 16 + (lane >> 2);
    const int colb = h * HD + (lane & 3) * 2;
#pragma unroll
    for (int nt = 0; nt < 8; nt++) {
        size_t o0 = r0g * DM + colb + nt * 8;
        size_t o1 = (r0g + 8) * DM + colb + nt * 8;
        *(uint32_t*)&Yf[o0] = cvt2h(accY[nt][0] * inv0, accY[nt][1] * inv0);
        *(uint32_t*)&Yf[o1] = cvt2h(accY[nt][2] * inv1, accY[nt][3] * inv1);
    }
}

// ---------------------------------------------------------------------------
extern "C" void kernel_launch(void* const* d_in, const int* in_sizes, int n_in,
                              void* d_out, int out_size)
{
    const float* hs = (const float*)d_in[0];
    const float* Wq = (const float*)d_in[1];
    const float* Wk = (const float*)d_in[2];
    const float* Wv = (const float*)d_in[3];
    const float* Wo = (const float*)d_in[4];
    float* out = (float*)d_out;

    __half *Xf, *Wf, *QKf, *Vf, *Yf, *Wof;
    cudaGetSymbolAddress((void**)&Xf, g_Xf);
    cudaGetSymbolAddress((void**)&Wf, g_Wf);
    cudaGetSymbolAddress((void**)&QKf, g_QKf);
    cudaGetSymbolAddress((void**)&Vf, g_Vf);
    cudaGetSymbolAddress((void**)&Yf, g_Yf);
    cudaGetSymbolAddress((void**)&Wof, g_Wof);

    cudaFuncSetAttribute(mma_proj, cudaFuncAttributeMaxDynamicSharedMemorySize, 2 * GSTG);
    cudaFuncSetAttribute(mma_out64, cudaFuncAttributeMaxDynamicSharedMemorySize, 2 * OSTG);
    cudaFuncSetAttribute(attn_mma, cudaFuncAttributeMaxDynamicSharedMemorySize, ASM_TOTAL);

    // All converts in one launch
    convert_all<<<(XN + NPROJ * DM + DM * DM) / 1024, 256>>>(
        hs, Wq, Wk, Wv, Wo, Xf, Wf, Wof);

    // Merged projection (CTA 128x128, occ 2)
    {
        dim3 g(NPROJ / 128, ROWS / 128);
        mma_proj<<<g, 256, 2 * GSTG>>>(Xf, Wf, QKf, Vf);
    }
    // Attention (exact R12 shape)
    {
        dim3 ga(LSEQ / 128, NH, BATCH);
        attn_mma<<<ga, 256, ASM_TOTAL>>>(QKf, Vf, Yf);
    }
    // Output projection (CTA 128x64, occ 4)
    {
        dim3 g(DM / 64, ROWS / 128);
        mma_out64<<<g, 256, 2 * OSTG>>>(Yf, Wof, out);
    }
}